// round 3
// baseline (speedup 1.0000x reference)
#include <cuda_runtime.h>
#include <cuda_bf16.h>
#include <math.h>

// ---------------------------------------------------------------------------
// LSTM: S=512, B=64, I=256, H=512
// out = [h_seq (S,B,H) | h_final (B,H) | c_final (B,H)]  (fp32)
// ---------------------------------------------------------------------------

#define S_LEN 512
#define BATCH 64
#define IN_DIM 256
#define HID 512
#define G4 2048              // 4*H
#define BH (BATCH*HID)       // 32768
#define BG (BATCH*G4)        // 131072
#define HPAD 516             // padded row stride (floats) for conflict-free smem
#define NCTA 128

// -------------------- device scratch (static: no allocs allowed) ------------
__device__ float g_xp[(size_t)S_LEN * BATCH * G4];   // 256 MB: x@Wx + bx + bh
__device__ float g_Wx[IN_DIM * G4];                  // 2 MB packed (K x 4H)
__device__ float g_WhT[(size_t)G4 * HID];            // 4 MB: WhT[col][k]
__device__ float g_bias[G4];                         // bx + bh
__device__ unsigned int g_flags[NCTA * 8];           // 32B-padded arrival flags

// -------------------- f32x2 helpers (Blackwell packed fp32) -----------------
__device__ __forceinline__ void fma2(unsigned long long& d,
                                     unsigned long long a,
                                     unsigned long long b) {
    asm("fma.rn.f32x2 %0, %1, %2, %0;" : "+l"(d) : "l"(a), "l"(b));
}
__device__ __forceinline__ unsigned long long dup2(float a) {
    unsigned long long d;
    asm("mov.b64 %0, {%1, %1};" : "=l"(d) : "f"(a));
    return d;
}
__device__ __forceinline__ float sum2(unsigned long long v) {
    float lo, hi;
    asm("mov.b64 {%0, %1}, %2;" : "=f"(lo), "=f"(hi) : "l"(v));
    return lo + hi;
}

// fast activations: ex2.approx + rcp.approx (rel err ~1e-6, safe vs 1e-3 tol)
__device__ __forceinline__ float fast_exp(float x) {
    float e;
    asm("ex2.approx.f32 %0, %1;" : "=f"(e) : "f"(x * 1.4426950408889634f));
    return e;
}
__device__ __forceinline__ float fast_rcp(float x) {
    float r;
    asm("rcp.approx.f32 %0, %1;" : "=f"(r) : "f"(x));
    return r;
}
__device__ __forceinline__ float fast_sigmoid(float x) {
    return fast_rcp(1.f + fast_exp(-x));
}
__device__ __forceinline__ float fast_tanh(float x) {
    return 2.f * fast_rcp(1.f + fast_exp(-2.f * x)) - 1.f;
}

__device__ __forceinline__ void cpasync16(unsigned dst, const void* src) {
    asm volatile("cp.async.cg.shared.global [%0], [%1], 16;"
                 :: "r"(dst), "l"(src));
}

// -------------------- init / pack kernels -----------------------------------
__global__ void bar_init_kernel() {
    int i = threadIdx.x;
    if (i < NCTA * 8) g_flags[i] = 0u;
}

__global__ void pack_wx_kernel(
    const float* __restrict__ Wf, const float* __restrict__ Wi,
    const float* __restrict__ Wo, const float* __restrict__ Wg,
    const float* __restrict__ bxf, const float* __restrict__ bhf,
    const float* __restrict__ bxi, const float* __restrict__ bhi,
    const float* __restrict__ bxo, const float* __restrict__ bho,
    const float* __restrict__ bxg, const float* __restrict__ bhg)
{
    int idx = blockIdx.x * blockDim.x + threadIdx.x;
    if (idx < IN_DIM * G4) {
        int k = idx >> 11;
        int col = idx & 2047;
        int g = col >> 9;
        int jj = col & 511;
        const float* W = (g == 0) ? Wf : (g == 1) ? Wi : (g == 2) ? Wo : Wg;
        g_Wx[idx] = W[k * HID + jj];
    }
    if (idx < G4) {
        int g = idx >> 9, jj = idx & 511;
        const float* bx = (g == 0) ? bxf : (g == 1) ? bxi : (g == 2) ? bxo : bxg;
        const float* bh = (g == 0) ? bhf : (g == 1) ? bhi : (g == 2) ? bho : bhg;
        g_bias[idx] = bx[jj] + bh[jj];
    }
}

__global__ void pack_wh_kernel(
    const float* __restrict__ Wf, const float* __restrict__ Wi,
    const float* __restrict__ Wo, const float* __restrict__ Wg)
{
    int idx = blockIdx.x * blockDim.x + threadIdx.x;
    if (idx < G4 * HID) {
        int col = idx >> 9;
        int k   = idx & 511;
        int g   = col >> 9;
        int jj  = col & 511;
        const float* W = (g == 0) ? Wf : (g == 1) ? Wi : (g == 2) ? Wo : Wg;
        g_WhT[idx] = W[k * HID + jj];   // WhT[col][k] = Wh[k][col]
    }
}

// -------------------- xproj: xp = x @ Wx_cat + bias --------------------------
__global__ __launch_bounds__(256) void xproj_kernel(const float* __restrict__ x)
{
    __shared__ float As[16][132];
    __shared__ float Bs[16][64];

    const int tid = threadIdx.x;
    const int tx = tid & 15;
    const int ty = tid >> 4;
    const int bm = blockIdx.y * 128;
    const int bn = blockIdx.x * 64;

    unsigned long long acc[8][2];
#pragma unroll
    for (int i = 0; i < 8; i++) { acc[i][0] = 0ull; acc[i][1] = 0ull; }

    const int a_m = tid >> 2;
    const int a_k = (tid & 3) << 2;
    const int b_r = tid >> 4;
    const int b_c = (tid & 15) << 2;

    const float* Aptr = x + (size_t)bm * IN_DIM;

    for (int kt = 0; kt < IN_DIM; kt += 16) {
        float4 av0 = *(const float4*)(Aptr + (size_t)a_m * IN_DIM + kt + a_k);
        float4 av1 = *(const float4*)(Aptr + (size_t)(a_m + 64) * IN_DIM + kt + a_k);
        float4 bv  = *(const float4*)(g_Wx + (size_t)(kt + b_r) * G4 + bn + b_c);

        As[a_k + 0][a_m] = av0.x; As[a_k + 1][a_m] = av0.y;
        As[a_k + 2][a_m] = av0.z; As[a_k + 3][a_m] = av0.w;
        As[a_k + 0][a_m + 64] = av1.x; As[a_k + 1][a_m + 64] = av1.y;
        As[a_k + 2][a_m + 64] = av1.z; As[a_k + 3][a_m + 64] = av1.w;
        *(float4*)&Bs[b_r][b_c] = bv;
        __syncthreads();

#pragma unroll
        for (int kk = 0; kk < 16; kk++) {
            float4 a0 = *(const float4*)&As[kk][ty * 8];
            float4 a1 = *(const float4*)&As[kk][ty * 8 + 4];
            ulonglong2 bb = *(const ulonglong2*)&Bs[kk][tx * 4];
            float av[8] = {a0.x, a0.y, a0.z, a0.w, a1.x, a1.y, a1.z, a1.w};
#pragma unroll
            for (int i = 0; i < 8; i++) {
                unsigned long long ad = dup2(av[i]);
                fma2(acc[i][0], ad, bb.x);
                fma2(acc[i][1], ad, bb.y);
            }
        }
        __syncthreads();
    }

    const int n0 = bn + tx * 4;
    float4 bias = *(const float4*)&g_bias[n0];
#pragma unroll
    for (int i = 0; i < 8; i++) {
        float l0, h0, l1, h1;
        asm("mov.b64 {%0, %1}, %2;" : "=f"(l0), "=f"(h0) : "l"(acc[i][0]));
        asm("mov.b64 {%0, %1}, %2;" : "=f"(l1), "=f"(h1) : "l"(acc[i][1]));
        float4 outv = make_float4(l0 + bias.x, h0 + bias.y, l1 + bias.z, h1 + bias.w);
        int m = bm + ty * 8 + i;
        *(float4*)&g_xp[(size_t)m * G4 + n0] = outv;
    }
}

// -------------------- recurrence: persistent, flag-array barrier -------------
// 128 CTAs x 256 threads. CTA owns hidden units j in [cta*4, cta*4+4).
// Thread = (b, u): b = tid>>2 (batch), u = tid&3 (unit). Computes all 4 gates
// of (b, j=cta*4+u): per k-iter 1 h-load + 4 w-loads (LDS.128), 8 FFMA2,
// two accumulator chains per gate. No shuffles. c lives in a register.
#define REC_SMEM ((64 * HPAD + 16 * HPAD) * 4)

__global__ __launch_bounds__(256, 1) void lstm_rec_kernel(float* __restrict__ out)
{
    extern __shared__ float sm[];
    float* h_s  = sm;                 // 64 * HPAD
    float* wh_s = sm + 64 * HPAD;     // 16 * HPAD

    const int tid = threadIdx.x;
    const int b   = tid >> 2;         // 0..63
    const int u   = tid & 3;          // 0..3
    const int cta = blockIdx.x;
    const int j   = (cta << 2) + u;

    // Load Wh slice once: wh_s[g*4+jr][k] = Wh[k][g*512 + cta*4 + jr]
    for (int idx = tid; idx < 16 * 128; idx += 256) {
        int r  = idx >> 7;
        int k4 = (idx & 127) << 2;
        int g  = r >> 2, jr = r & 3;
        int col = g * HID + (cta << 2) + jr;
        float4 v = *(const float4*)&g_WhT[(size_t)col * HID + k4];
        *(float4*)&wh_s[r * HPAD + k4] = v;
    }
    __syncthreads();

    const ulonglong2* hp = (const ulonglong2*)(h_s + b * HPAD);
    const ulonglong2* w0 = (const ulonglong2*)(wh_s + (u + 0)  * HPAD);  // f
    const ulonglong2* w1 = (const ulonglong2*)(wh_s + (u + 4)  * HPAD);  // i
    const ulonglong2* w2 = (const ulonglong2*)(wh_s + (u + 8)  * HPAD);  // o
    const ulonglong2* w3 = (const ulonglong2*)(wh_s + (u + 12) * HPAD);  // g

    const unsigned hbase = (unsigned)__cvta_generic_to_shared(h_s);

    const size_t xof = (size_t)b * G4 + j;          // gate f col
    // prefetch xp for t=0
    float c0 = g_xp[xof];
    float c1 = g_xp[xof + 512];
    float c2 = g_xp[xof + 1024];
    float c3 = g_xp[xof + 1536];

    float cval = 0.f;

    for (int t = 0; t < S_LEN; t++) {
        if (t > 0) {
            const float4* src = (const float4*)(out + (size_t)(t - 1) * BH);
#pragma unroll
            for (int i = 0; i < 32; i++) {
                int idx = tid + (i << 8);
                int row = idx >> 7;
                int col = (idx & 127) << 2;
                cpasync16(hbase + (unsigned)(row * HPAD + col) * 4u,
                          (const void*)(src + idx));
            }
            asm volatile("cp.async.commit_group;");
            asm volatile("cp.async.wait_group 0;" ::: "memory");
            __syncthreads();
        }

        // prefetch xp for t+1 (hides DRAM latency under dot loop)
        float n0 = 0.f, n1 = 0.f, n2 = 0.f, n3 = 0.f;
        if (t + 1 < S_LEN) {
            size_t nb = (size_t)(t + 1) * BG + xof;
            n0 = g_xp[nb]; n1 = g_xp[nb + 512];
            n2 = g_xp[nb + 1024]; n3 = g_xp[nb + 1536];
        }

        float gf, gi, go, gg;
        if (t > 0) {
            // two chains per gate (split .x/.y): hides FFMA latency fully
            unsigned long long aA0 = 0ull, aB0 = 0ull, aA1 = 0ull, aB1 = 0ull;
            unsigned long long aA2 = 0ull, aB2 = 0ull, aA3 = 0ull, aB3 = 0ull;
#pragma unroll 8
            for (int k = 0; k < 128; k++) {
                ulonglong2 hv = hp[k];
                ulonglong2 wf = w0[k];
                ulonglong2 wi = w1[k];
                ulonglong2 wo = w2[k];
                ulonglong2 wg = w3[k];
                fma2(aA0, hv.x, wf.x); fma2(aB0, hv.y, wf.y);
                fma2(aA1, hv.x, wi.x); fma2(aB1, hv.y, wi.y);
                fma2(aA2, hv.x, wo.x); fma2(aB2, hv.y, wo.y);
                fma2(aA3, hv.x, wg.x); fma2(aB3, hv.y, wg.y);
            }
            gf = sum2(aA0) + sum2(aB0) + c0;
            gi = sum2(aA1) + sum2(aB1) + c1;
            go = sum2(aA2) + sum2(aB2) + c2;
            gg = sum2(aA3) + sum2(aB3) + c3;
        } else {
            gf = c0; gi = c1; go = c2; gg = c3;
        }
        c0 = n0; c1 = n1; c2 = n2; c3 = n3;

        float fg = fast_sigmoid(gf);
        float ig = fast_sigmoid(gi);
        float og = fast_sigmoid(go);
        float gt = fast_tanh(gg);
        cval = fg * cval + ig * gt;
        float hval = og * fast_tanh(cval);

        out[(size_t)t * BH + b * HID + j] = hval;

        if (t < S_LEN - 1) {
            // ---- flag-array grid barrier ----
            __syncthreads();                 // all out-stores in CTA done
            if (tid == 0) {
                asm volatile("st.release.gpu.global.u32 [%0], %1;"
                             :: "l"(&g_flags[cta * 8]), "r"((unsigned)(t + 1))
                             : "memory");
            }
            if (tid < NCTA) {
                unsigned target = (unsigned)(t + 1);
                unsigned v;
                while (true) {
                    asm volatile("ld.acquire.gpu.global.u32 %0, [%1];"
                                 : "=r"(v) : "l"(&g_flags[tid * 8]) : "memory");
                    if (v >= target) break;
                    __nanosleep(32);
                }
            }
            __syncthreads();
        } else {
            out[(size_t)S_LEN * BH + b * HID + j] = hval;          // h_final
            out[(size_t)S_LEN * BH + BH + b * HID + j] = cval;     // c_final
        }
    }
}

// -------------------- launch ------------------------------------------------
extern "C" void kernel_launch(void* const* d_in, const int* in_sizes, int n_in,
                              void* d_out, int out_size)
{
    (void)in_sizes; (void)n_in; (void)out_size;
    const float* x   = (const float*)d_in[0];
    const float* Wxf = (const float*)d_in[1];
    const float* bxf = (const float*)d_in[2];
    const float* Whf = (const float*)d_in[3];
    const float* bhf = (const float*)d_in[4];
    const float* Wxi = (const float*)d_in[5];
    const float* bxi = (const float*)d_in[6];
    const float* Whi = (const float*)d_in[7];
    const float* bhi = (const float*)d_in[8];
    const float* Wxo = (const float*)d_in[9];
    const float* bxo = (const float*)d_in[10];
    const float* Who = (const float*)d_in[11];
    const float* bho = (const float*)d_in[12];
    const float* Wxg = (const float*)d_in[13];
    const float* bxg = (const float*)d_in[14];
    const float* Whg = (const float*)d_in[15];
    const float* bhg = (const float*)d_in[16];
    float* out = (float*)d_out;

    bar_init_kernel<<<1, 1024>>>();
    pack_wx_kernel<<<(IN_DIM * G4 + 255) / 256, 256>>>(
        Wxf, Wxi, Wxo, Wxg, bxf, bhf, bxi, bhi, bxo, bho, bxg, bhg);
    pack_wh_kernel<<<(G4 * HID + 255) / 256, 256>>>(Whf, Whi, Who, Whg);

    dim3 gproj(G4 / 64, (S_LEN * BATCH) / 128);
    xproj_kernel<<<gproj, 256>>>(x);

    static bool attr_set = false;
    if (!attr_set) {
        cudaFuncSetAttribute(lstm_rec_kernel,
                             cudaFuncAttributeMaxDynamicSharedMemorySize, REC_SMEM);
        attr_set = true;
    }
    lstm_rec_kernel<<<NCTA, 256, REC_SMEM>>>(out);
}

// round 4
// speedup vs baseline: 1.6202x; 1.6202x over previous
#include <cuda_runtime.h>
#include <cuda_bf16.h>
#include <math.h>

// ---------------------------------------------------------------------------
// LSTM: S=512, B=64, I=256, H=512
// out = [h_seq (S,B,H) | h_final (B,H) | c_final (B,H)]  (fp32)
// ---------------------------------------------------------------------------

#define S_LEN 512
#define BATCH 64
#define IN_DIM 256
#define HID 512
#define G4 2048              // 4*H
#define BH (BATCH*HID)       // 32768
#define BG (BATCH*G4)        // 131072
#define HPAD 516             // padded row stride (floats): 2064B = 16 mod 128
#define NCTA 128

// -------------------- device scratch (static: no allocs allowed) ------------
__device__ float g_xp[(size_t)S_LEN * BATCH * G4];   // 256 MB: x@Wx + bx + bh
__device__ float g_Wx[IN_DIM * G4];                  // packed (K x 4H)
__device__ float g_WhT[(size_t)G4 * HID];            // WhT[col][k]
__device__ float g_bias[G4];                         // bx + bh
__device__ unsigned int g_barc[4 * 32];              // per-bg counters, 128B apart

// -------------------- f32x2 helpers (Blackwell packed fp32) -----------------
__device__ __forceinline__ void fma2(unsigned long long& d,
                                     unsigned long long a,
                                     unsigned long long b) {
    asm("fma.rn.f32x2 %0, %1, %2, %0;" : "+l"(d) : "l"(a), "l"(b));
}
__device__ __forceinline__ unsigned long long dup2(float a) {
    unsigned long long d;
    asm("mov.b64 %0, {%1, %1};" : "=l"(d) : "f"(a));
    return d;
}
__device__ __forceinline__ float sum2(unsigned long long v) {
    float lo, hi;
    asm("mov.b64 {%0, %1}, %2;" : "=f"(lo), "=f"(hi) : "l"(v));
    return lo + hi;
}

// fast activations: ex2.approx + rcp.approx (rel err ~1e-6, safe vs 1e-3 tol)
__device__ __forceinline__ float fast_exp(float x) {
    float e;
    asm("ex2.approx.f32 %0, %1;" : "=f"(e) : "f"(x * 1.4426950408889634f));
    return e;
}
__device__ __forceinline__ float fast_rcp(float x) {
    float r;
    asm("rcp.approx.f32 %0, %1;" : "=f"(r) : "f"(x));
    return r;
}
__device__ __forceinline__ float fast_sigmoid(float x) {
    return fast_rcp(1.f + fast_exp(-x));
}
__device__ __forceinline__ float fast_tanh(float x) {
    return 2.f * fast_rcp(1.f + fast_exp(-2.f * x)) - 1.f;
}

__device__ __forceinline__ void cpasync16(unsigned dst, const void* src) {
    asm volatile("cp.async.cg.shared.global [%0], [%1], 16;"
                 :: "r"(dst), "l"(src));
}

// -------------------- init / pack kernels -----------------------------------
__global__ void bar_init_kernel() {
    int i = threadIdx.x;
    if (i < 4 * 32) g_barc[i] = 0u;
}

__global__ void pack_wx_kernel(
    const float* __restrict__ Wf, const float* __restrict__ Wi,
    const float* __restrict__ Wo, const float* __restrict__ Wg,
    const float* __restrict__ bxf, const float* __restrict__ bhf,
    const float* __restrict__ bxi, const float* __restrict__ bhi,
    const float* __restrict__ bxo, const float* __restrict__ bho,
    const float* __restrict__ bxg, const float* __restrict__ bhg)
{
    int idx = blockIdx.x * blockDim.x + threadIdx.x;
    if (idx < IN_DIM * G4) {
        int k = idx >> 11;
        int col = idx & 2047;
        int g = col >> 9;
        int jj = col & 511;
        const float* W = (g == 0) ? Wf : (g == 1) ? Wi : (g == 2) ? Wo : Wg;
        g_Wx[idx] = W[k * HID + jj];
    }
    if (idx < G4) {
        int g = idx >> 9, jj = idx & 511;
        const float* bx = (g == 0) ? bxf : (g == 1) ? bxi : (g == 2) ? bxo : bxg;
        const float* bh = (g == 0) ? bhf : (g == 1) ? bhi : (g == 2) ? bho : bhg;
        g_bias[idx] = bx[jj] + bh[jj];
    }
}

__global__ void pack_wh_kernel(
    const float* __restrict__ Wf, const float* __restrict__ Wi,
    const float* __restrict__ Wo, const float* __restrict__ Wg)
{
    int idx = blockIdx.x * blockDim.x + threadIdx.x;
    if (idx < G4 * HID) {
        int col = idx >> 9;
        int k   = idx & 511;
        int g   = col >> 9;
        int jj  = col & 511;
        const float* W = (g == 0) ? Wf : (g == 1) ? Wi : (g == 2) ? Wo : Wg;
        g_WhT[idx] = W[k * HID + jj];   // WhT[col][k] = Wh[k][col]
    }
}

// -------------------- xproj: xp = x @ Wx_cat + bias --------------------------
__global__ __launch_bounds__(256) void xproj_kernel(const float* __restrict__ x)
{
    __shared__ float As[16][132];
    __shared__ float Bs[16][64];

    const int tid = threadIdx.x;
    const int tx = tid & 15;
    const int ty = tid >> 4;
    const int bm = blockIdx.y * 128;
    const int bn = blockIdx.x * 64;

    unsigned long long acc[8][2];
#pragma unroll
    for (int i = 0; i < 8; i++) { acc[i][0] = 0ull; acc[i][1] = 0ull; }

    const int a_m = tid >> 2;
    const int a_k = (tid & 3) << 2;
    const int b_r = tid >> 4;
    const int b_c = (tid & 15) << 2;

    const float* Aptr = x + (size_t)bm * IN_DIM;

    for (int kt = 0; kt < IN_DIM; kt += 16) {
        float4 av0 = *(const float4*)(Aptr + (size_t)a_m * IN_DIM + kt + a_k);
        float4 av1 = *(const float4*)(Aptr + (size_t)(a_m + 64) * IN_DIM + kt + a_k);
        float4 bv  = *(const float4*)(g_Wx + (size_t)(kt + b_r) * G4 + bn + b_c);

        As[a_k + 0][a_m] = av0.x; As[a_k + 1][a_m] = av0.y;
        As[a_k + 2][a_m] = av0.z; As[a_k + 3][a_m] = av0.w;
        As[a_k + 0][a_m + 64] = av1.x; As[a_k + 1][a_m + 64] = av1.y;
        As[a_k + 2][a_m + 64] = av1.z; As[a_k + 3][a_m + 64] = av1.w;
        *(float4*)&Bs[b_r][b_c] = bv;
        __syncthreads();

#pragma unroll
        for (int kk = 0; kk < 16; kk++) {
            float4 a0 = *(const float4*)&As[kk][ty * 8];
            float4 a1 = *(const float4*)&As[kk][ty * 8 + 4];
            ulonglong2 bb = *(const ulonglong2*)&Bs[kk][tx * 4];
            float av[8] = {a0.x, a0.y, a0.z, a0.w, a1.x, a1.y, a1.z, a1.w};
#pragma unroll
            for (int i = 0; i < 8; i++) {
                unsigned long long ad = dup2(av[i]);
                fma2(acc[i][0], ad, bb.x);
                fma2(acc[i][1], ad, bb.y);
            }
        }
        __syncthreads();
    }

    const int n0 = bn + tx * 4;
    float4 bias = *(const float4*)&g_bias[n0];
#pragma unroll
    for (int i = 0; i < 8; i++) {
        float l0, h0, l1, h1;
        asm("mov.b64 {%0, %1}, %2;" : "=f"(l0), "=f"(h0) : "l"(acc[i][0]));
        asm("mov.b64 {%0, %1}, %2;" : "=f"(l1), "=f"(h1) : "l"(acc[i][1]));
        float4 outv = make_float4(l0 + bias.x, h0 + bias.y, l1 + bias.z, h1 + bias.w);
        int m = bm + ty * 8 + i;
        *(float4*)&g_xp[(size_t)m * G4 + n0] = outv;
    }
}

// -------------------- recurrence: 2-D persistent, group barriers -------------
// 128 CTAs = 4 batch-groups (bg: 16 batches) x 32 unit-groups (ug: 16 units).
// Per CTA: 64 gate-rows (r = g*16+u) of Wh in smem (132KB), h slice 16x512.
// Dot threads: warp covers 8 rows (full 128B w phase) x 4 batches; thread =
// 2 batches x 2 rows = 4 dots, 8 FFMA2 + 4 LDS.128 per k-iter (4096-cyc balanced).
// Gates regrouped via smem gbuf; activation threads = (b,u) own c in register.
// Barrier: per-bg red.release counter, 32 arrivals, tid0 polls.
#define REC_SMEM ((80 * HPAD + 64 * 17) * 4)

__global__ __launch_bounds__(256, 1) void lstm_rec_kernel(float* __restrict__ out)
{
    extern __shared__ float sm[];
    float* h_s  = sm;                  // 16 * HPAD
    float* wh_s = sm + 16 * HPAD;      // 64 * HPAD
    float* gbuf = sm + 80 * HPAD;      // 64 * 17

    const int tid = threadIdx.x;
    const int cta = blockIdx.x;
    const int ug  = cta & 31;          // unit group: units [ug*16, ug*16+16)
    const int bg  = cta >> 5;          // batch group: batches [bg*16, +16)

    // ---- load Wh slice: wh_s[r][k] = Wh[k][(r>>4)*512 + ug*16 + (r&15)] ----
    for (int idx = tid; idx < 64 * 128; idx += 256) {
        int r  = idx >> 7;
        int k4 = (idx & 127) << 2;
        int col = (r >> 4) * HID + (ug << 4) + (r & 15);
        float4 v = *(const float4*)&g_WhT[(size_t)col * HID + k4];
        *(float4*)&wh_s[r * HPAD + k4] = v;
    }
    __syncthreads();

    // ---- dot-thread mapping ----
    const int w    = tid >> 5;
    const int lane = tid & 31;
    const int rl   = lane & 7;
    const int bl   = lane >> 3;
    const int r1   = (w & 3) * 8 + rl;       // [0,32)
    const int r2   = r1 + 32;                // [32,64)
    const int db1  = (w >> 2) * 8 + bl;      // local batch {0..3}|{8..11}
    const int db2  = db1 + 4;

    const ulonglong2* hp1 = (const ulonglong2*)(h_s + db1 * HPAD);
    const ulonglong2* hp2 = (const ulonglong2*)(h_s + db2 * HPAD);
    const ulonglong2* wp1 = (const ulonglong2*)(wh_s + r1 * HPAD);
    const ulonglong2* wp2 = (const ulonglong2*)(wh_s + r2 * HPAD);

    // ---- activation-thread mapping: (b,u) ----
    const int ab = tid >> 4;                 // local batch 0..15
    const int au = tid & 15;                 // local unit 0..15
    const int gb = bg * 16 + ab;             // global batch
    const int gj = (ug << 4) + au;           // global hidden unit

    const unsigned hbase = (unsigned)__cvta_generic_to_shared(h_s);
    unsigned int* barp = &g_barc[bg * 32];

    const size_t xof = (size_t)gb * G4 + gj;
    float c0 = g_xp[xof];
    float c1 = g_xp[xof + 512];
    float c2 = g_xp[xof + 1024];
    float c3 = g_xp[xof + 1536];

    float cval = 0.f;

    for (int t = 0; t < S_LEN; t++) {
        if (t > 0) {
            // stage h(t-1)[bg batches] : 16 rows x 512 floats = 32KB
            const float4* src = (const float4*)(out + (size_t)(t - 1) * BH
                                                + (size_t)(bg * 16) * HID);
#pragma unroll
            for (int i = 0; i < 8; i++) {            // 2048 float4 / 256 thr
                int idx = tid + (i << 8);
                int row = idx >> 7;
                int col = (idx & 127) << 2;
                cpasync16(hbase + (unsigned)(row * HPAD + col) * 4u,
                          (const void*)(src + idx));
            }
            asm volatile("cp.async.commit_group;");
            asm volatile("cp.async.wait_group 0;" ::: "memory");
            __syncthreads();
        }

        // prefetch xp for t+1 (hidden under dot loop)
        float n0 = 0.f, n1 = 0.f, n2 = 0.f, n3 = 0.f;
        if (t + 1 < S_LEN) {
            size_t nb = (size_t)(t + 1) * BG + xof;
            n0 = g_xp[nb]; n1 = g_xp[nb + 512];
            n2 = g_xp[nb + 1024]; n3 = g_xp[nb + 1536];
        }

        if (t > 0) {
            unsigned long long a11x = 0ull, a11y = 0ull, a12x = 0ull, a12y = 0ull;
            unsigned long long a21x = 0ull, a21y = 0ull, a22x = 0ull, a22y = 0ull;
#pragma unroll 8
            for (int k = 0; k < 128; k++) {
                ulonglong2 h1 = hp1[k];
                ulonglong2 h2 = hp2[k];
                ulonglong2 w1 = wp1[k];
                ulonglong2 w2 = wp2[k];
                fma2(a11x, h1.x, w1.x); fma2(a11y, h1.y, w1.y);
                fma2(a12x, h1.x, w2.x); fma2(a12y, h1.y, w2.y);
                fma2(a21x, h2.x, w1.x); fma2(a21y, h2.y, w1.y);
                fma2(a22x, h2.x, w2.x); fma2(a22y, h2.y, w2.y);
            }
            gbuf[r1 * 17 + db1] = sum2(a11x) + sum2(a11y);
            gbuf[r2 * 17 + db1] = sum2(a12x) + sum2(a12y);
            gbuf[r1 * 17 + db2] = sum2(a21x) + sum2(a21y);
            gbuf[r2 * 17 + db2] = sum2(a22x) + sum2(a22y);
            __syncthreads();
        }

        // ---- activation: thread (ab, au) ----
        float gf = c0, gi = c1, go = c2, gg = c3;
        if (t > 0) {
            gf += gbuf[(au +  0) * 17 + ab];
            gi += gbuf[(au + 16) * 17 + ab];
            go += gbuf[(au + 32) * 17 + ab];
            gg += gbuf[(au + 48) * 17 + ab];
        }
        c0 = n0; c1 = n1; c2 = n2; c3 = n3;

        float fg = fast_sigmoid(gf);
        float ig = fast_sigmoid(gi);
        float og = fast_sigmoid(go);
        float gt = fast_tanh(gg);
        cval = fg * cval + ig * gt;
        float hval = og * fast_tanh(cval);

        out[(size_t)t * BH + (size_t)gb * HID + gj] = hval;

        if (t < S_LEN - 1) {
            // ---- per-bg group barrier: 32 arrivals on one counter ----
            __syncthreads();
            if (tid == 0) {
                asm volatile("red.release.gpu.global.add.u32 [%0], 1;"
                             :: "l"(barp) : "memory");
                unsigned target = (unsigned)(t + 1) * 32u;
                unsigned v;
                while (true) {
                    asm volatile("ld.acquire.gpu.global.u32 %0, [%1];"
                                 : "=r"(v) : "l"(barp) : "memory");
                    if (v >= target) break;
                    __nanosleep(20);
                }
            }
            __syncthreads();
        } else {
            out[(size_t)S_LEN * BH + (size_t)gb * HID + gj] = hval;        // h_f
            out[(size_t)S_LEN * BH + BH + (size_t)gb * HID + gj] = cval;   // c_f
        }
    }
}

// -------------------- launch ------------------------------------------------
extern "C" void kernel_launch(void* const* d_in, const int* in_sizes, int n_in,
                              void* d_out, int out_size)
{
    (void)in_sizes; (void)n_in; (void)out_size;
    const float* x   = (const float*)d_in[0];
    const float* Wxf = (const float*)d_in[1];
    const float* bxf = (const float*)d_in[2];
    const float* Whf = (const float*)d_in[3];
    const float* bhf = (const float*)d_in[4];
    const float* Wxi = (const float*)d_in[5];
    const float* bxi = (const float*)d_in[6];
    const float* Whi = (const float*)d_in[7];
    const float* bhi = (const float*)d_in[8];
    const float* Wxo = (const float*)d_in[9];
    const float* bxo = (const float*)d_in[10];
    const float* Who = (const float*)d_in[11];
    const float* bho = (const float*)d_in[12];
    const float* Wxg = (const float*)d_in[13];
    const float* bxg = (const float*)d_in[14];
    const float* Whg = (const float*)d_in[15];
    const float* bhg = (const float*)d_in[16];
    float* out = (float*)d_out;

    bar_init_kernel<<<1, 128>>>();
    pack_wx_kernel<<<(IN_DIM * G4 + 255) / 256, 256>>>(
        Wxf, Wxi, Wxo, Wxg, bxf, bhf, bxi, bhi, bxo, bho, bxg, bhg);
    pack_wh_kernel<<<(G4 * HID + 255) / 256, 256>>>(Whf, Whi, Who, Whg);

    dim3 gproj(G4 / 64, (S_LEN * BATCH) / 128);
    xproj_kernel<<<gproj, 256>>>(x);

    static bool attr_set = false;
    if (!attr_set) {
        cudaFuncSetAttribute(lstm_rec_kernel,
                             cudaFuncAttributeMaxDynamicSharedMemorySize, REC_SMEM);
        attr_set = true;
    }
    lstm_rec_kernel<<<NCTA, 256, REC_SMEM>>>(out);
}